// round 4
// baseline (speedup 1.0000x reference)
#include <cuda_runtime.h>
#include <cuda_bf16.h>
#include <cstdint>

#define B_ 64
#define S_ 512
#define D_ 512
#define CHK 16          // k-chunk in f32 elems
#define NCH 32          // 512/16
#define NSTAGE 4
#define STW 20          // f32 stage row stride (words): conflict-free LDS.128
#define SROW 24         // bf16 tile row stride (elems = 12 words): conflict-free

// dynamic smem layout (bytes)
#define OFF_STA   0                       // 4 stages * 128*STW*4 = 40960
#define OFF_STB   40960                   // 40960
#define OFF_AS    81920                   // 128*SROW*2 = 6144
#define OFF_BS    88064                   // 6144
#define OFF_INVA  94208                   // 512
#define OFF_INVB  94720                   // 512
#define OFF_MISC  95232                   // isLast + red[8]
#define SMEM_BYTES 98304

__device__ unsigned g_rowmax[B_ * S_];
__device__ unsigned g_colmax[B_ * S_];
__device__ int g_n1[B_];
__device__ int g_n2[B_];
__device__ int g_total[B_];
__device__ int g_cnt[B_];

__device__ __forceinline__ unsigned enc_f(float f) {
    unsigned u = __float_as_uint(f);
    return (u & 0x80000000u) ? ~u : (u | 0x80000000u);
}
__device__ __forceinline__ float dec_f(unsigned u) {
    return (u & 0x80000000u) ? __uint_as_float(u ^ 0x80000000u) : __uint_as_float(~u);
}

__global__ void prep_kernel(const int* __restrict__ m1, const int* __restrict__ m2) {
    int b = blockIdx.x, t = threadIdx.x;
    int s1 = 0, s2 = 0;
    for (int i = t; i < S_; i += 256) {
        s1 += m1[b * S_ + i];
        s2 += m2[b * S_ + i];
        g_rowmax[b * S_ + i] = 0u;
        g_colmax[b * S_ + i] = 0u;
    }
#pragma unroll
    for (int o = 16; o; o >>= 1) {
        s1 += __shfl_xor_sync(0xffffffffu, s1, o);
        s2 += __shfl_xor_sync(0xffffffffu, s2, o);
    }
    __shared__ int r1[8], r2[8];
    if ((t & 31) == 0) { r1[t >> 5] = s1; r2[t >> 5] = s2; }
    __syncthreads();
    if (t == 0) {
        int a = 0, c = 0;
#pragma unroll
        for (int w = 0; w < 8; w++) { a += r1[w]; c += r2[w]; }
        g_n1[b] = a;
        g_n2[b] = c;
        g_total[b] = ((a + 127) >> 7) * ((c + 127) >> 7);
        g_cnt[b] = 0;
    }
}

extern __shared__ __align__(16) char smem_raw[];

__global__ void __launch_bounds__(256, 2) sim_kernel(const float* __restrict__ E1,
                                                     const float* __restrict__ E2,
                                                     float* __restrict__ out) {
    int b = blockIdx.z;
    int n1 = g_n1[b], n2 = g_n2[b];
    int i0 = blockIdx.y * 128, j0 = blockIdx.x * 128;
    if (i0 >= n1 || j0 >= n2) return;

    float* stA = (float*)(smem_raw + OFF_STA);
    float* stB = (float*)(smem_raw + OFF_STB);
    __nv_bfloat16* As = (__nv_bfloat16*)(smem_raw + OFF_AS);
    __nv_bfloat16* Bs = (__nv_bfloat16*)(smem_raw + OFF_BS);
    float* invA = (float*)(smem_raw + OFF_INVA);
    float* invB = (float*)(smem_raw + OFF_INVB);
    int* isLastP = (int*)(smem_raw + OFF_MISC);
    float* red = (float*)(smem_raw + OFF_MISC + 16);

    int tid = threadIdx.x, lane = tid & 31, warp = tid >> 5;
    int wm = warp >> 2, wn = warp & 3;

    // loader/convert mapping: t<128 -> A row t ; t>=128 -> B row t-128
    bool isA = tid < 128;
    int lrow = isA ? tid : (tid - 128);
    const float* gsrc = (isA ? E1 + ((size_t)b * S_ + i0 + lrow) * D_
                             : E2 + ((size_t)b * S_ + j0 + lrow) * D_);
    float* stMine = isA ? stA : stB;
    uint32_t stBase = (uint32_t)__cvta_generic_to_shared(stMine) + lrow * STW * 4;

    float acc[4][4][4];
#pragma unroll
    for (int a = 0; a < 4; a++)
#pragma unroll
        for (int c = 0; c < 4; c++)
#pragma unroll
            for (int d = 0; d < 4; d++) acc[a][c][d] = 0.f;

    float ss = 0.f;

    auto issue = [&](int kc) {
        int s = kc & (NSTAGE - 1);
        const float* src = gsrc + kc * CHK;
        uint32_t dst = stBase + s * 128 * STW * 4;
#pragma unroll
        for (int seg = 0; seg < 4; seg++) {
            asm volatile("cp.async.cg.shared.global [%0], [%1], 16;\n"
                         ::"r"(dst + seg * 16), "l"(src + seg * 4));
        }
        asm volatile("cp.async.commit_group;\n");
    };

    // prologue
    issue(0); issue(1); issue(2);

#pragma unroll 1
    for (int kc = 0; kc < NCH; kc++) {
        int s = kc & (NSTAGE - 1);
        asm volatile("cp.async.wait_group 2;\n");
        __syncthreads();

        // convert: f32 stage -> ss + bf16 tile
        {
            const float* srow = stMine + s * 128 * STW + lrow * STW;
            uint32_t w[8];
#pragma unroll
            for (int seg = 0; seg < 4; seg++) {
                float4 v = *(const float4*)(srow + seg * 4);
                ss += v.x * v.x + v.y * v.y + v.z * v.z + v.w * v.w;
                __nv_bfloat162 p0 = __floats2bfloat162_rn(v.x, v.y);
                __nv_bfloat162 p1 = __floats2bfloat162_rn(v.z, v.w);
                w[seg * 2 + 0] = *(unsigned*)&p0;
                w[seg * 2 + 1] = *(unsigned*)&p1;
            }
            __nv_bfloat16* drow = (isA ? As : Bs) + lrow * SROW;
            *(uint4*)(drow) = make_uint4(w[0], w[1], w[2], w[3]);
            *(uint4*)(drow + 8) = make_uint4(w[4], w[5], w[6], w[7]);
        }
        __syncthreads();

        if (kc + NSTAGE - 1 < NCH) issue(kc + NSTAGE - 1);
        else asm volatile("cp.async.commit_group;\n");   // keep group count stable

        // mma on bf16 tile (k=16)
        uint32_t af[4][4];
#pragma unroll
        for (int tm = 0; tm < 4; tm++) {
            int row = wm * 64 + tm * 16 + (lane & 15);
            int col = (lane >> 4) * 8;
            uint32_t addr = (uint32_t)__cvta_generic_to_shared(&As[row * SROW + col]);
            asm volatile("ldmatrix.sync.aligned.m8n8.x4.shared.b16 {%0,%1,%2,%3},[%4];\n"
                         : "=r"(af[tm][0]), "=r"(af[tm][1]), "=r"(af[tm][2]), "=r"(af[tm][3])
                         : "r"(addr));
        }
        uint32_t bfr[4][2];
#pragma unroll
        for (int tn = 0; tn < 4; tn++) {
            int l = lane & 15;
            int rowb = wn * 32 + tn * 8 + (l & 7);
            int colb = (l >> 3) * 8;
            uint32_t addr = (uint32_t)__cvta_generic_to_shared(&Bs[rowb * SROW + colb]);
            asm volatile("ldmatrix.sync.aligned.m8n8.x2.shared.b16 {%0,%1},[%2];\n"
                         : "=r"(bfr[tn][0]), "=r"(bfr[tn][1])
                         : "r"(addr));
        }
#pragma unroll
        for (int tm = 0; tm < 4; tm++)
#pragma unroll
            for (int tn = 0; tn < 4; tn++)
                asm volatile(
                    "mma.sync.aligned.m16n8k16.row.col.f32.bf16.bf16.f32 "
                    "{%0,%1,%2,%3},{%4,%5,%6,%7},{%8,%9},{%0,%1,%2,%3};\n"
                    : "+f"(acc[tm][tn][0]), "+f"(acc[tm][tn][1]),
                      "+f"(acc[tm][tn][2]), "+f"(acc[tm][tn][3])
                    : "r"(af[tm][0]), "r"(af[tm][1]), "r"(af[tm][2]), "r"(af[tm][3]),
                      "r"(bfr[tn][0]), "r"(bfr[tn][1]));
    }

    // inverse norms (x / max(sqrt(ss),1e-8)); t<128 owns full A row, else B row
    {
        float iv = 1.0f / fmaxf(sqrtf(ss), 1e-8f);
        if (isA) invA[lrow] = iv; else invB[lrow] = iv;
    }
    __syncthreads();

    const float NEGINF = -3.0e38f;

    // row max over valid j
#pragma unroll
    for (int tm = 0; tm < 4; tm++) {
#pragma unroll
        for (int rr = 0; rr < 2; rr++) {
            float v = NEGINF;
#pragma unroll
            for (int tn = 0; tn < 4; tn++) {
#pragma unroll
                for (int cc = 0; cc < 2; cc++) {
                    int jl = wn * 32 + tn * 8 + (lane & 3) * 2 + cc;
                    if (j0 + jl < n2) v = fmaxf(v, acc[tm][tn][rr * 2 + cc] * invB[jl]);
                }
            }
            v = fmaxf(v, __shfl_xor_sync(0xffffffffu, v, 1));
            v = fmaxf(v, __shfl_xor_sync(0xffffffffu, v, 2));
            if ((lane & 3) == 0) {
                int il = wm * 64 + tm * 16 + (lane >> 2) + rr * 8;
                if (i0 + il < n1) atomicMax(&g_rowmax[b * S_ + i0 + il], enc_f(v * invA[il]));
            }
        }
    }

    // col max over valid i
#pragma unroll
    for (int tn = 0; tn < 4; tn++) {
#pragma unroll
        for (int cc = 0; cc < 2; cc++) {
            float v = NEGINF;
#pragma unroll
            for (int tm = 0; tm < 4; tm++) {
#pragma unroll
                for (int rr = 0; rr < 2; rr++) {
                    int il = wm * 64 + tm * 16 + (lane >> 2) + rr * 8;
                    if (i0 + il < n1) v = fmaxf(v, acc[tm][tn][rr * 2 + cc] * invA[il]);
                }
            }
            v = fmaxf(v, __shfl_xor_sync(0xffffffffu, v, 4));
            v = fmaxf(v, __shfl_xor_sync(0xffffffffu, v, 8));
            v = fmaxf(v, __shfl_xor_sync(0xffffffffu, v, 16));
            if (lane < 4) {
                int jl = wn * 32 + tn * 8 + lane * 2 + cc;
                if (j0 + jl < n2) atomicMax(&g_colmax[b * S_ + j0 + jl], enc_f(v * invB[jl]));
            }
        }
    }

    // last tile of this batch reduces and writes out[b]
    __threadfence();
    __syncthreads();
    if (tid == 0) {
        int c = atomicAdd(&g_cnt[b], 1);
        *isLastP = (c == g_total[b] - 1);
    }
    __syncthreads();
    if (!*isLastP) return;

    float s = 0.f;
    for (int i = tid; i < n1; i += 256) s += dec_f(__ldcg(&g_rowmax[b * S_ + i]));
    for (int j = tid; j < n2; j += 256) s += dec_f(__ldcg(&g_colmax[b * S_ + j]));
#pragma unroll
    for (int o = 16; o; o >>= 1) s += __shfl_xor_sync(0xffffffffu, s, o);
    if ((tid & 31) == 0) red[tid >> 5] = s;
    __syncthreads();
    if (tid == 0) {
        float tot = 0.f;
#pragma unroll
        for (int w = 0; w < 8; w++) tot += red[w];
        out[b] = tot / (float)(n1 + n2);
    }
}

extern "C" void kernel_launch(void* const* d_in, const int* in_sizes, int n_in,
                              void* d_out, int out_size) {
    (void)in_sizes; (void)n_in; (void)out_size;
    const float* e1 = (const float*)d_in[0];
    const float* e2 = (const float*)d_in[1];
    const int* m1 = (const int*)d_in[2];
    const int* m2 = (const int*)d_in[3];

    cudaFuncSetAttribute(sim_kernel, cudaFuncAttributeMaxDynamicSharedMemorySize, SMEM_BYTES);

    prep_kernel<<<B_, 256>>>(m1, m2);
    sim_kernel<<<dim3(4, 4, B_), 256, SMEM_BYTES>>>(e1, e2, (float*)d_out);
}

// round 5
// speedup vs baseline: 2.3980x; 2.3980x over previous
#include <cuda_runtime.h>
#include <cuda_bf16.h>
#include <cstdint>

#define B_ 64
#define S_ 512
#define D_ 512
#define NCHUNK 16     // 512 / 32
#define TMK 32        // k-chunk in bf16 elems
#define NSTAGE 4
#define SROW 40       // smem row stride bf16 (32 data + 8 pad): conflict-free ldmatrix

// dynamic smem: 4 stages x (As | Bs), each 128*SROW bf16 = 10240 B
#define STAGE_BYTES (2 * 128 * SROW * 2)   // 20480
#define SMEM_BYTES  (NSTAGE * STAGE_BYTES) // 81920

__device__ __nv_bfloat16 g_e1[B_ * S_ * D_];   // normalized bf16
__device__ __nv_bfloat16 g_e2[B_ * S_ * D_];
__device__ unsigned g_rowmax[B_ * S_];
__device__ unsigned g_colmax[B_ * S_];
__device__ int g_n1[B_];
__device__ int g_n2[B_];
__device__ int g_total[B_];
__device__ int g_cnt[B_];

__device__ __forceinline__ unsigned enc_f(float f) {
    unsigned u = __float_as_uint(f);
    return (u & 0x80000000u) ? ~u : (u | 0x80000000u);
}
__device__ __forceinline__ float dec_f(unsigned u) {
    return (u & 0x80000000u) ? __uint_as_float(u ^ 0x80000000u) : __uint_as_float(~u);
}

// ---- kernel 1: L2-normalize rows -> bf16 scratch; blocks 0..63 also do prep ----
__global__ void norm_kernel(const float* __restrict__ in1, const float* __restrict__ in2,
                            const int* __restrict__ m1, const int* __restrict__ m2) {
    int t = threadIdx.x;

    // fold prep into the first 64 blocks (in addition to their row work)
    if (blockIdx.x < B_) {
        int b = blockIdx.x;
        int s1 = 0, s2 = 0;
        for (int i = t; i < S_; i += 256) {
            s1 += m1[b * S_ + i];
            s2 += m2[b * S_ + i];
            g_rowmax[b * S_ + i] = 0u;
            g_colmax[b * S_ + i] = 0u;
        }
#pragma unroll
        for (int o = 16; o; o >>= 1) {
            s1 += __shfl_xor_sync(0xffffffffu, s1, o);
            s2 += __shfl_xor_sync(0xffffffffu, s2, o);
        }
        __shared__ int r1[8], r2[8];
        if ((t & 31) == 0) { r1[t >> 5] = s1; r2[t >> 5] = s2; }
        __syncthreads();
        if (t == 0) {
            int a = 0, c = 0;
#pragma unroll
            for (int w = 0; w < 8; w++) { a += r1[w]; c += r2[w]; }
            g_n1[b] = a;
            g_n2[b] = c;
            g_total[b] = ((a + 127) >> 7) * ((c + 127) >> 7);
            g_cnt[b] = 0;
        }
    }

    int row = blockIdx.x * 8 + (t >> 5);
    int lane = t & 31;
    const float* src;
    __nv_bfloat16* dst;
    if (row < B_ * S_) {
        src = in1 + (size_t)row * D_;
        dst = g_e1 + (size_t)row * D_;
    } else {
        int r = row - B_ * S_;
        src = in2 + (size_t)r * D_;
        dst = g_e2 + (size_t)r * D_;
    }
    float4 v[4];
    float ss = 0.f;
#pragma unroll
    for (int q = 0; q < 4; q++) {
        v[q] = ((const float4*)src)[lane + q * 32];
        ss += v[q].x * v[q].x + v[q].y * v[q].y + v[q].z * v[q].z + v[q].w * v[q].w;
    }
#pragma unroll
    for (int o = 16; o; o >>= 1) ss += __shfl_xor_sync(0xffffffffu, ss, o);
    float inv = 1.0f / fmaxf(sqrtf(ss), 1e-8f);
#pragma unroll
    for (int q = 0; q < 4; q++) {
        __nv_bfloat162 h0 = __floats2bfloat162_rn(v[q].x * inv, v[q].y * inv);
        __nv_bfloat162 h1 = __floats2bfloat162_rn(v[q].z * inv, v[q].w * inv);
        ((__nv_bfloat162*)dst)[(lane + q * 32) * 2 + 0] = h0;
        ((__nv_bfloat162*)dst)[(lane + q * 32) * 2 + 1] = h1;
    }
}

extern __shared__ __align__(16) char smem_raw[];

// ---- kernel 2: bf16 GEMM tile + masked row/col max + fused final reduce ----
__global__ void __launch_bounds__(256, 2) sim_kernel(float* __restrict__ out) {
    int b = blockIdx.z;
    int n1 = g_n1[b], n2 = g_n2[b];
    int i0 = blockIdx.y * 128, j0 = blockIdx.x * 128;
    if (i0 >= n1 || j0 >= n2) return;   // prefix-mask tile skipping

    int tid = threadIdx.x, lane = tid & 31, warp = tid >> 5;
    int wm = warp >> 2, wn = warp & 3;   // 2 x 4 warps, warp tile 64x32

    const __nv_bfloat16* Ag = g_e1 + ((size_t)b * S_ + i0) * D_;
    const __nv_bfloat16* Bg = g_e2 + ((size_t)b * S_ + j0) * D_;

    uint32_t smemBase = (uint32_t)__cvta_generic_to_shared(smem_raw);

    float acc[4][4][4];
#pragma unroll
    for (int a = 0; a < 4; a++)
#pragma unroll
        for (int c = 0; c < 4; c++)
#pragma unroll
            for (int d = 0; d < 4; d++) acc[a][c][d] = 0.f;

    auto issue = [&](int kc) {
        int st = kc & (NSTAGE - 1);
        uint32_t aBase = smemBase + st * STAGE_BYTES;
        uint32_t bBase = aBase + 128 * SROW * 2;
        int k0 = kc * TMK;
#pragma unroll
        for (int r = 0; r < 2; r++) {
            int idx = tid + r * 256;
            int row = idx >> 2, seg = idx & 3;
            const void* gpa = Ag + (size_t)row * D_ + k0 + seg * 8;
            asm volatile("cp.async.cg.shared.global [%0], [%1], 16;\n"
                         ::"r"(aBase + (row * SROW + seg * 8) * 2), "l"(gpa));
            const void* gpb = Bg + (size_t)row * D_ + k0 + seg * 8;
            asm volatile("cp.async.cg.shared.global [%0], [%1], 16;\n"
                         ::"r"(bBase + (row * SROW + seg * 8) * 2), "l"(gpb));
        }
        asm volatile("cp.async.commit_group;\n");
    };

    issue(0); issue(1); issue(2);

#pragma unroll 1
    for (int kc = 0; kc < NCHUNK; kc++) {
        int st = kc & (NSTAGE - 1);
        asm volatile("cp.async.wait_group 2;\n");
        __syncthreads();   // all threads see chunk kc landed; all reads of stage kc-1 done

        if (kc + 3 < NCHUNK) issue(kc + 3);
        else asm volatile("cp.async.commit_group;\n");   // keep group count uniform

        uint32_t aBase = smemBase + st * STAGE_BYTES;
        uint32_t bBase = aBase + 128 * SROW * 2;

#pragma unroll
        for (int ks = 0; ks < 2; ks++) {
            uint32_t af[4][4];
#pragma unroll
            for (int tm = 0; tm < 4; tm++) {
                int row = wm * 64 + tm * 16 + (lane & 15);
                int col = ks * 16 + (lane >> 4) * 8;
                asm volatile("ldmatrix.sync.aligned.m8n8.x4.shared.b16 {%0,%1,%2,%3},[%4];\n"
                             : "=r"(af[tm][0]), "=r"(af[tm][1]), "=r"(af[tm][2]), "=r"(af[tm][3])
                             : "r"(aBase + (row * SROW + col) * 2));
            }
            uint32_t bfr[4][2];
#pragma unroll
            for (int tn = 0; tn < 4; tn++) {
                int l = lane & 15;
                int rowb = wn * 32 + tn * 8 + (l & 7);
                int colb = ks * 16 + (l >> 3) * 8;
                asm volatile("ldmatrix.sync.aligned.m8n8.x2.shared.b16 {%0,%1},[%2];\n"
                             : "=r"(bfr[tn][0]), "=r"(bfr[tn][1])
                             : "r"(bBase + (rowb * SROW + colb) * 2));
            }
#pragma unroll
            for (int tm = 0; tm < 4; tm++)
#pragma unroll
                for (int tn = 0; tn < 4; tn++)
                    asm volatile(
                        "mma.sync.aligned.m16n8k16.row.col.f32.bf16.bf16.f32 "
                        "{%0,%1,%2,%3},{%4,%5,%6,%7},{%8,%9},{%0,%1,%2,%3};\n"
                        : "+f"(acc[tm][tn][0]), "+f"(acc[tm][tn][1]),
                          "+f"(acc[tm][tn][2]), "+f"(acc[tm][tn][3])
                        : "r"(af[tm][0]), "r"(af[tm][1]), "r"(af[tm][2]), "r"(af[tm][3]),
                          "r"(bfr[tn][0]), "r"(bfr[tn][1]));
        }
    }

    // ---- fused masked reductions ----
    const float NEGINF = -3.0e38f;

#pragma unroll
    for (int tm = 0; tm < 4; tm++) {
#pragma unroll
        for (int rr = 0; rr < 2; rr++) {
            float v = NEGINF;
#pragma unroll
            for (int tn = 0; tn < 4; tn++) {
#pragma unroll
                for (int cc = 0; cc < 2; cc++) {
                    int jl = wn * 32 + tn * 8 + (lane & 3) * 2 + cc;
                    if (j0 + jl < n2) v = fmaxf(v, acc[tm][tn][rr * 2 + cc]);
                }
            }
            v = fmaxf(v, __shfl_xor_sync(0xffffffffu, v, 1));
            v = fmaxf(v, __shfl_xor_sync(0xffffffffu, v, 2));
            if ((lane & 3) == 0) {
                int il = wm * 64 + tm * 16 + (lane >> 2) + rr * 8;
                if (i0 + il < n1) atomicMax(&g_rowmax[b * S_ + i0 + il], enc_f(v));
            }
        }
    }

#pragma unroll
    for (int tn = 0; tn < 4; tn++) {
#pragma unroll
        for (int cc = 0; cc < 2; cc++) {
            float v = NEGINF;
#pragma unroll
            for (int tm = 0; tm < 4; tm++) {
#pragma unroll
                for (int rr = 0; rr < 2; rr++) {
                    int il = wm * 64 + tm * 16 + (lane >> 2) + rr * 8;
                    if (i0 + il < n1) v = fmaxf(v, acc[tm][tn][rr * 2 + cc]);
                }
            }
            v = fmaxf(v, __shfl_xor_sync(0xffffffffu, v, 4));
            v = fmaxf(v, __shfl_xor_sync(0xffffffffu, v, 8));
            v = fmaxf(v, __shfl_xor_sync(0xffffffffu, v, 16));
            if (lane < 4) {
                int jl = wn * 32 + tn * 8 + lane * 2 + cc;
                if (j0 + jl < n2) atomicMax(&g_colmax[b * S_ + j0 + jl], enc_f(v));
            }
        }
    }

    // ---- last tile of this batch reduces and writes out[b] ----
    __shared__ int isLast;
    __shared__ float red[8];
    __threadfence();
    __syncthreads();
    if (tid == 0) {
        int c = atomicAdd(&g_cnt[b], 1);
        isLast = (c == g_total[b] - 1);
    }
    __syncthreads();
    if (!isLast) return;

    float s = 0.f;
    for (int i = tid; i < n1; i += 256) s += dec_f(__ldcg(&g_rowmax[b * S_ + i]));
    for (int j = tid; j < n2; j += 256) s += dec_f(__ldcg(&g_colmax[b * S_ + j]));
#pragma unroll
    for (int o = 16; o; o >>= 1) s += __shfl_xor_sync(0xffffffffu, s, o);
    if ((tid & 31) == 0) red[tid >> 5] = s;
    __syncthreads();
    if (tid == 0) {
        float tot = 0.f;
#pragma unroll
        for (int w = 0; w < 8; w++) tot += red[w];
        out[b] = tot / (float)(n1 + n2);
    }
}

extern "C" void kernel_launch(void* const* d_in, const int* in_sizes, int n_in,
                              void* d_out, int out_size) {
    (void)in_sizes; (void)n_in; (void)out_size;
    const float* e1 = (const float*)d_in[0];
    const float* e2 = (const float*)d_in[1];
    const int* m1 = (const int*)d_in[2];
    const int* m2 = (const int*)d_in[3];

    cudaFuncSetAttribute(sim_kernel, cudaFuncAttributeMaxDynamicSharedMemorySize, SMEM_BYTES);

    norm_kernel<<<(2 * B_ * S_) / 8, 256>>>(e1, e2, m1, m2);
    sim_kernel<<<dim3(4, 4, B_), 256, SMEM_BYTES>>>((float*)d_out);
}

// round 12
// speedup vs baseline: 2.7844x; 1.1611x over previous
#include <cuda_runtime.h>
#include <cuda_bf16.h>
#include <cstdint>

#define B_ 64
#define S_ 512
#define D_ 512
#define KCHK 64       // k-chunk in bf16 elems (128B rows, SW128 swizzle, no padding)
#define NCHK 8        // 512 / 64
#define NST 3         // pipeline stages

// per stage: A tile 128x64 bf16 (16KB) + B tile 128x64 (16KB)
#define STAGE_BYTES 32768
#define SMEM_BYTES  (NST * STAGE_BYTES + 64)   // + isLast/red scratch

__device__ __nv_bfloat16 g_e1[B_ * S_ * D_];
__device__ __nv_bfloat16 g_e2[B_ * S_ * D_];
__device__ unsigned g_rowmax[B_ * S_];
__device__ unsigned g_colmax[B_ * S_];
__device__ int g_n1[B_];
__device__ int g_n2[B_];
__device__ int g_total[B_];
__device__ int g_cnt[B_];

__device__ __forceinline__ unsigned enc_f(float f) {
    unsigned u = __float_as_uint(f);
    return (u & 0x80000000u) ? ~u : (u | 0x80000000u);
}
__device__ __forceinline__ float dec_f(unsigned u) {
    return (u & 0x80000000u) ? __uint_as_float(u ^ 0x80000000u) : __uint_as_float(~u);
}
__device__ __forceinline__ uint32_t sw128(uint32_t off) { return off ^ ((off >> 3) & 0x70); }

// ---- kernel 1: L2-normalize rows -> bf16 scratch; blocks 0..63 also do prep ----
__global__ void norm_kernel(const float* __restrict__ in1, const float* __restrict__ in2,
                            const int* __restrict__ m1, const int* __restrict__ m2) {
    int t = threadIdx.x;
    if (blockIdx.x < B_) {
        int b = blockIdx.x;
        int s1 = 0, s2 = 0;
        for (int i = t; i < S_; i += 256) {
            s1 += m1[b * S_ + i];
            s2 += m2[b * S_ + i];
            g_rowmax[b * S_ + i] = 0u;
            g_colmax[b * S_ + i] = 0u;
        }
#pragma unroll
        for (int o = 16; o; o >>= 1) {
            s1 += __shfl_xor_sync(0xffffffffu, s1, o);
            s2 += __shfl_xor_sync(0xffffffffu, s2, o);
        }
        __shared__ int r1[8], r2[8];
        if ((t & 31) == 0) { r1[t >> 5] = s1; r2[t >> 5] = s2; }
        __syncthreads();
        if (t == 0) {
            int a = 0, c = 0;
#pragma unroll
            for (int w = 0; w < 8; w++) { a += r1[w]; c += r2[w]; }
            g_n1[b] = a;
            g_n2[b] = c;
            g_total[b] = ((a + 127) >> 7) * ((c + 127) >> 7);
            g_cnt[b] = 0;
        }
    }

    int row = blockIdx.x * 8 + (t >> 5);
    int lane = t & 31;
    const float* src;
    __nv_bfloat16* dst;
    if (row < B_ * S_) {
        src = in1 + (size_t)row * D_;
        dst = g_e1 + (size_t)row * D_;
    } else {
        int r = row - B_ * S_;
        src = in2 + (size_t)r * D_;
        dst = g_e2 + (size_t)r * D_;
    }
    float4 v[4];
    float ss = 0.f;
#pragma unroll
    for (int q = 0; q < 4; q++) {
        v[q] = ((const float4*)src)[lane + q * 32];
        ss += v[q].x * v[q].x + v[q].y * v[q].y + v[q].z * v[q].z + v[q].w * v[q].w;
    }
#pragma unroll
    for (int o = 16; o; o >>= 1) ss += __shfl_xor_sync(0xffffffffu, ss, o);
    float inv = 1.0f / fmaxf(sqrtf(ss), 1e-8f);
#pragma unroll
    for (int q = 0; q < 4; q++) {
        __nv_bfloat162 h0 = __floats2bfloat162_rn(v[q].x * inv, v[q].y * inv);
        __nv_bfloat162 h1 = __floats2bfloat162_rn(v[q].z * inv, v[q].w * inv);
        ((__nv_bfloat162*)dst)[(lane + q * 32) * 2 + 0] = h0;
        ((__nv_bfloat162*)dst)[(lane + q * 32) * 2 + 1] = h1;
    }
}

extern __shared__ __align__(16) char smem_raw[];

// ---- kernel 2: bf16 mma.sync GEMM (SW128, 64-wide chunks) + masked max + final reduce ----
__global__ void __launch_bounds__(256, 2) sim_kernel(float* __restrict__ out) {
    int b = blockIdx.z;
    int n1 = g_n1[b], n2 = g_n2[b];
    int i0 = blockIdx.y * 128, j0 = blockIdx.x * 128;
    if (i0 >= n1 || j0 >= n2) return;   // prefix-mask tile skipping

    int tid = threadIdx.x, lane = tid & 31, warp = tid >> 5;
    int wm = warp >> 2, wn = warp & 3;   // 2 x 4 warps, warp tile 64x32

    const __nv_bfloat16* Ag = g_e1 + ((size_t)b * S_ + i0) * D_;
    const __nv_bfloat16* Bg = g_e2 + ((size_t)b * S_ + j0) * D_;

    uint32_t sb = (uint32_t)__cvta_generic_to_shared(smem_raw);
    int* isLastP = (int*)(smem_raw + NST * STAGE_BYTES);
    float* red = (float*)(smem_raw + NST * STAGE_BYTES + 16);

    float acc[4][4][4];
#pragma unroll
    for (int a = 0; a < 4; a++)
#pragma unroll
        for (int c = 0; c < 4; c++)
#pragma unroll
            for (int d = 0; d < 4; d++) acc[a][c][d] = 0.f;

    // loader: 2048 16B segs per chunk-pair (A+B), 8 per thread; 8 tids = one 128B row
    auto issue = [&](int kc) {
        int st = kc % NST;
        uint32_t aB = sb + st * STAGE_BYTES;
        uint32_t bB = aB + 16384;
        const __nv_bfloat16* Asrc = Ag + kc * KCHK;
        const __nv_bfloat16* Bsrc = Bg + kc * KCHK;
#pragma unroll
        for (int i = 0; i < 4; i++) {
            int g = tid + i * 256;
            int row = g >> 3, seg = g & 7;
            uint32_t so = sw128(row * 128 + seg * 16);
            const void* ga = Asrc + (size_t)row * D_ + seg * 8;
            asm volatile("cp.async.cg.shared.global [%0], [%1], 16;\n" ::"r"(aB + so), "l"(ga));
            const void* gb = Bsrc + (size_t)row * D_ + seg * 8;
            asm volatile("cp.async.cg.shared.global [%0], [%1], 16;\n" ::"r"(bB + so), "l"(gb));
        }
        asm volatile("cp.async.commit_group;\n");
    };

    issue(0); issue(1);

#pragma unroll 1
    for (int kc = 0; kc < NCHK; kc++) {
        int st = kc % NST;
        asm volatile("cp.async.wait_group 1;\n");
        __syncthreads();   // chunk kc resident for all; stage of kc-1 fully consumed

        if (kc + 2 < NCHK) issue(kc + 2);
        else asm volatile("cp.async.commit_group;\n");   // keep group count uniform

        uint32_t aB = sb + st * STAGE_BYTES;
        uint32_t bB = aB + 16384;

#pragma unroll
        for (int ks = 0; ks < 4; ks++) {
            // A fragments: 4 x ldmatrix.x4 (16 rows x 16 cols each)
            uint32_t af[4][4];
#pragma unroll
            for (int tm = 0; tm < 4; tm++) {
                int row = wm * 64 + tm * 16 + (lane & 15);
                uint32_t so = sw128(row * 128 + ks * 32 + (lane >> 4) * 16);
                asm volatile("ldmatrix.sync.aligned.m8n8.x4.shared.b16 {%0,%1,%2,%3},[%4];\n"
                             : "=r"(af[tm][0]), "=r"(af[tm][1]), "=r"(af[tm][2]), "=r"(af[tm][3])
                             : "r"(aB + so));
            }
            // B fragments: 2 x ldmatrix.x4, each covering two n-tiles (16 rows)
            uint32_t bfr[4][2];
#pragma unroll
            for (int tnp = 0; tnp < 2; tnp++) {
                int rowb = wn * 32 + tnp * 16 + ((lane >> 4) << 3) + (lane & 7);
                uint32_t so = sw128(rowb * 128 + ks * 32 + ((lane >> 3) & 1) * 16);
                asm volatile("ldmatrix.sync.aligned.m8n8.x4.shared.b16 {%0,%1,%2,%3},[%4];\n"
                             : "=r"(bfr[tnp * 2][0]), "=r"(bfr[tnp * 2][1]),
                               "=r"(bfr[tnp * 2 + 1][0]), "=r"(bfr[tnp * 2 + 1][1])
                             : "r"(bB + so));
            }
#pragma unroll
            for (int tm = 0; tm < 4; tm++)
#pragma unroll
                for (int tn = 0; tn < 4; tn++)
                    asm volatile(
                        "mma.sync.aligned.m16n8k16.row.col.f32.bf16.bf16.f32 "
                        "{%0,%1,%2,%3},{%4,%5,%6,%7},{%8,%9},{%0,%1,%2,%3};\n"
                        : "+f"(acc[tm][tn][0]), "+f"(acc[tm][tn][1]),
                          "+f"(acc[tm][tn][2]), "+f"(acc[tm][tn][3])
                        : "r"(af[tm][0]), "r"(af[tm][1]), "r"(af[tm][2]), "r"(af[tm][3]),
                          "r"(bfr[tn][0]), "r"(bfr[tn][1]));
        }
    }

    // ---- fused masked reductions ----
    const float NEGINF = -3.0e38f;

#pragma unroll
    for (int tm = 0; tm < 4; tm++) {
#pragma unroll
        for (int rr = 0; rr < 2; rr++) {
            float v = NEGINF;
#pragma unroll
            for (int tn = 0; tn < 4; tn++) {
#pragma unroll
                for (int cc = 0; cc < 2; cc++) {
                    int jl = wn * 32 + tn * 8 + (lane & 3) * 2 + cc;
                    if (j0 + jl < n2) v = fmaxf(v, acc[tm][tn][rr * 2 + cc]);
                }
            }
            v = fmaxf(v, __shfl_xor_sync(0xffffffffu, v, 1));
            v = fmaxf(v, __shfl_xor_sync(0xffffffffu, v, 2));
            if ((lane & 3) == 0) {
                int il = wm * 64 + tm * 16 + (lane >> 2) + rr * 8;
                if (i0 + il < n1) atomicMax(&g_rowmax[b * S_ + i0 + il], enc_f(v));
            }
        }
    }

#pragma unroll
    for (int tn = 0; tn < 4; tn++) {
#pragma unroll
        for (int cc = 0; cc < 2; cc++) {
            float v = NEGINF;
#pragma unroll
            for (int tm = 0; tm < 4; tm++) {
#pragma unroll
                for (int rr = 0; rr < 2; rr++) {
                    int il = wm * 64 + tm * 16 + (lane >> 2) + rr * 8;
                    if (i0 + il < n1) v = fmaxf(v, acc[tm][tn][rr * 2 + cc]);
                }
            }
            v = fmaxf(v, __shfl_xor_sync(0xffffffffu, v, 4));
            v = fmaxf(v, __shfl_xor_sync(0xffffffffu, v, 8));
            v = fmaxf(v, __shfl_xor_sync(0xffffffffu, v, 16));
            if (lane < 4) {
                int jl = wn * 32 + tn * 8 + lane * 2 + cc;
                if (j0 + jl < n2) atomicMax(&g_colmax[b * S_ + j0 + jl], enc_f(v));
            }
        }
    }

    // ---- last tile of this batch reduces and writes out[b] ----
    __threadfence();
    __syncthreads();
    if (tid == 0) {
        int c = atomicAdd(&g_cnt[b], 1);
        *isLastP = (c == g_total[b] - 1);
    }
    __syncthreads();
    if (!*isLastP) return;

    float s = 0.f;
    for (int i = tid; i < n1; i += 256) s += dec_f(__ldcg(&g_rowmax[b * S_ + i]));
    for (int j = tid; j < n2; j += 256) s += dec_f(__ldcg(&g_colmax[b * S_ + j]));
#pragma unroll
    for (int o = 16; o; o >>= 1) s += __shfl_xor_sync(0xffffffffu, s, o);
    if ((tid & 31) == 0) red[tid >> 5] = s;
    __syncthreads();
    if (tid == 0) {
        float tot = 0.f;
#pragma unroll
        for (int w = 0; w < 8; w++) tot += red[w];
        out[b] = tot / (float)(n1 + n2);
    }
}

extern "C" void kernel_launch(void* const* d_in, const int* in_sizes, int n_in,
                              void* d_out, int out_size) {
    (void)in_sizes; (void)n_in; (void)out_size;
    const float* e1 = (const float*)d_in[0];
    const float* e2 = (const float*)d_in[1];
    const int* m1 = (const int*)d_in[2];
    const int* m2 = (const int*)d_in[3];

    cudaFuncSetAttribute(sim_kernel, cudaFuncAttributeMaxDynamicSharedMemorySize, SMEM_BYTES);

    norm_kernel<<<(2 * B_ * S_) / 8, 256>>>(e1, e2, m1, m2);
    sim_kernel<<<dim3(4, 4, B_), 256, SMEM_BYTES>>>((float*)d_out);
}